// round 11
// baseline (speedup 1.0000x reference)
#include <cuda_runtime.h>

// ---------------------------------------------------------------------------
// Output = [B=128, T=512, 66]; all B rows identical (decoder ignores encoder,
// zero init state, constant first input emb[0]). fc folds into the recurrence:
//   g_{t+1} = Wc @ h_t + b_comb,  Wc = dec_W_ih @ fc_W + dec_W_hh  (264 x 66)
//   g_1     = dec_W_ih @ emb[0] + (dec_b_ih + dec_b_hh)
// The autonomous decoder map settles to a fixed point; every PER steps the
// leaders compare (h,c) against a PER-step-old snapshot (tol 1e-5). Once
// settled, remaining rows are a periodic extension of the last PER rows.
//
// SINGLE persistent kernel, grid = 148 blocks (<= SM count => all co-resident
// => intra-grid spin sync is deadlock-free), 544 threads:
//   Phase A: blocks 1..147 fold rows (1-2 each, 8-way k-split) -> cnt++
//   Phase B: block 0 spins on cnt==147, runs recurrence (R1 layout, threads
//            0..263, everyone keeps hitting barriers), publishes flag
//   Phase C: all blocks spin on flag, then write one 512-float4 x 16-row
//            output tile each (136 tiles), with inline periodic tail
//   Last block to finish resets cnt/flag/done -> graph-replay safe.
// ---------------------------------------------------------------------------

#define DEC_H 66
#define G4    264        // 4 * DEC_H
#define EMBED 128
#define HPAD  68         // DEC_H padded to a multiple of 4
#define MAXT  1024
#define PER   4          // convergence window / fill period
#define BROWS 16         // batch rows written per bcast thread
#define NBLK  148
#define NTHR  544

__device__ __align__(16) float g_Wc[G4 * HPAD];   // folded matrix, padded rows
__device__ float g_bias[G4];
__device__ float g_gx0[G4];
__device__ __align__(16) float g_hist[MAXT * DEC_H];
__device__ int g_tstop;
__device__ int g_cnt  = 0;   // phase A completions
__device__ int g_flag = 0;   // recurrence done
__device__ int g_done = 0;   // phase C completions (for reset)

typedef unsigned long long ull;

__device__ __forceinline__ void fma2(ull& acc, ull a, ull b) {
    asm("fma.rn.f32x2 %0, %1, %2, %0;" : "+l"(acc) : "l"(a), "l"(b));
}
__device__ __forceinline__ float2 up2(ull v) {
    float2 r;
    asm("mov.b64 {%0, %1}, %2;" : "=f"(r.x), "=f"(r.y) : "l"(v));
    return r;
}
__device__ __forceinline__ float fast_sigmoid(float x) {
    float e;
    asm("ex2.approx.f32 %0, %1;" : "=f"(e) : "f"(-1.4426950408889634f * x));
    float r;
    asm("rcp.approx.f32 %0, %1;" : "=f"(r) : "f"(1.0f + e));
    return r;
}
__device__ __forceinline__ float fast_tanh(float x) {
    x = fminf(20.0f, fmaxf(-20.0f, x));
    float e;
    asm("ex2.approx.f32 %0, %1;" : "=f"(e) : "f"(2.885390081777927f * x));
    float r;
    asm("rcp.approx.f32 %0, %1;" : "=f"(r) : "f"(e + 1.0f));
    return (e - 1.0f) * r;
}

__global__ __launch_bounds__(NTHR, 1) void mega_kernel(
        float* __restrict__ out,
        const float* __restrict__ Wih,
        const float* __restrict__ Whh,
        const float* __restrict__ bih,
        const float* __restrict__ bhh,
        const float* __restrict__ fcW,
        const float* __restrict__ fcb,
        const float* __restrict__ emb,
        int rowlen4, int T) {
    const int bid = blockIdx.x;
    const int tid = threadIdx.x;

    __shared__ float wrow[EMBED];
    __shared__ float part[8][HPAD];
    __shared__ __align__(16) float hsm[HPAD];
    __shared__ float act[G4];

    if (bid != 0) {
        // ================= Phase A: fold rows =================
        const int grp = tid / HPAD;        // 0..7 -> embed chunk of 16
        const int d   = tid - grp * HPAD;  // 0..67
        for (int j = bid - 1; j < G4; j += NBLK - 1) {
            if (tid < EMBED) wrow[tid] = Wih[j * EMBED + tid];
            __syncthreads();

            const int e0 = grp * 16;
            float s0 = 0.f, s1 = 0.f, s2 = 0.f, s3 = 0.f;
            float s4 = 0.f, s5 = 0.f, s6 = 0.f, s7 = 0.f;
            if (d < DEC_H) {
#pragma unroll
                for (int e = e0; e < e0 + 16; e += 8) {
                    s0 = fmaf(wrow[e + 0], fcW[(e + 0) * DEC_H + d], s0);
                    s1 = fmaf(wrow[e + 1], fcW[(e + 1) * DEC_H + d], s1);
                    s2 = fmaf(wrow[e + 2], fcW[(e + 2) * DEC_H + d], s2);
                    s3 = fmaf(wrow[e + 3], fcW[(e + 3) * DEC_H + d], s3);
                    s4 = fmaf(wrow[e + 4], fcW[(e + 4) * DEC_H + d], s4);
                    s5 = fmaf(wrow[e + 5], fcW[(e + 5) * DEC_H + d], s5);
                    s6 = fmaf(wrow[e + 6], fcW[(e + 6) * DEC_H + d], s6);
                    s7 = fmaf(wrow[e + 7], fcW[(e + 7) * DEC_H + d], s7);
                }
            } else {
                // d==66: fc_b path (bias), d==67: emb[0] path (gx0)
                const float* vec = (d == DEC_H) ? fcb : emb;
#pragma unroll
                for (int e = e0; e < e0 + 16; e += 8) {
                    s0 = fmaf(wrow[e + 0], vec[e + 0], s0);
                    s1 = fmaf(wrow[e + 1], vec[e + 1], s1);
                    s2 = fmaf(wrow[e + 2], vec[e + 2], s2);
                    s3 = fmaf(wrow[e + 3], vec[e + 3], s3);
                    s4 = fmaf(wrow[e + 4], vec[e + 4], s4);
                    s5 = fmaf(wrow[e + 5], vec[e + 5], s5);
                    s6 = fmaf(wrow[e + 6], vec[e + 6], s6);
                    s7 = fmaf(wrow[e + 7], vec[e + 7], s7);
                }
            }
            part[grp][d] = ((s0 + s1) + (s2 + s3)) + ((s4 + s5) + (s6 + s7));
            __syncthreads();

            if (tid < HPAD) {
                float sum = ((part[0][tid] + part[1][tid]) +
                             (part[2][tid] + part[3][tid])) +
                            ((part[4][tid] + part[5][tid]) +
                             (part[6][tid] + part[7][tid]));
                if (tid < DEC_H) {
                    g_Wc[j * HPAD + tid] = sum + Whh[j * DEC_H + tid];
                } else {
                    g_Wc[j * HPAD + tid] = 0.0f;      // padding column
                    float bb = bih[j] + bhh[j];
                    if (tid == DEC_H) g_bias[j] = sum + bb;
                    else              g_gx0[j]  = sum + bb;
                }
            }
            __syncthreads();   // protect wrow/part before next row
        }
        if (tid == 0) {
            __threadfence();
            atomicAdd(&g_cnt, 1);
        }

        // wait for recurrence result
        if (tid == 0) {
            while (*(volatile int*)&g_flag == 0) __nanosleep(32);
        }
        __syncthreads();
        __threadfence();
    } else {
        // ================= Phase B: recurrence (block 0) =================
        if (tid == 0) {
            while (*(volatile int*)&g_cnt < NBLK - 1) __nanosleep(32);
        }
        __syncthreads();
        __threadfence();

        const int j = tid;
        ull wv[34];
        float bias = 0.0f, gx0 = 0.0f;
        if (j < G4) {
            const ull* wsrc = reinterpret_cast<const ull*>(g_Wc) + j * 34;
#pragma unroll
            for (int k = 0; k < 34; k++) wv[k] = wsrc[k];
            bias = g_bias[j];
            gx0  = g_gx0[j];
        }
        if (j < HPAD) hsm[j] = 0.0f;
        float cst = 0.0f;
        float hP = 0.0f, cP = 0.0f;
        int tstop = T;
        __syncthreads();

        const ulonglong2* h2 = reinterpret_cast<const ulonglong2*>(hsm);

        for (int t = 0; t < T; t++) {
            if (j < G4) {
                ull a0 = 0ull, a1 = 0ull, a2 = 0ull, a3 = 0ull;
#pragma unroll
                for (int k = 0; k < 17; k++) {
                    ulonglong2 hv = h2[k];     // broadcast LDS.128
                    if (k & 1) {
                        fma2(a2, wv[2 * k], hv.x);
                        fma2(a3, wv[2 * k + 1], hv.y);
                    } else {
                        fma2(a0, wv[2 * k], hv.x);
                        fma2(a1, wv[2 * k + 1], hv.y);
                    }
                }
                // fold pairs
                asm("add.rn.f32x2 %0, %0, %1;" : "+l"(a0) : "l"(a2));
                asm("add.rn.f32x2 %0, %0, %1;" : "+l"(a1) : "l"(a3));
                asm("add.rn.f32x2 %0, %0, %1;" : "+l"(a0) : "l"(a1));
                float2 s = up2(a0);
                float g = (t == 0 ? gx0 : bias) + s.x + s.y;
                float a = (j < 2 * DEC_H || j >= 3 * DEC_H) ? fast_sigmoid(g)
                                                            : fast_tanh(g);
                act[j] = a;
            }
            __syncthreads();

            float hnew = 0.0f;
            if (j < DEC_H) {
                float iv = act[j];
                float fv = act[j + DEC_H];
                float gv = act[j + 2 * DEC_H];
                float ov = act[j + 3 * DEC_H];
                cst = fmaf(fv, cst, iv * gv);
                hnew = ov * fast_tanh(cst);
                hsm[j] = hnew;
                g_hist[t * DEC_H + j] = hnew;
            }

            if ((t & (PER - 1)) == (PER - 1)) {
                int moving = 0;
                if (j < DEC_H) {
                    if (t >= 2 * PER - 1) {
                        float dh = fabsf(hnew - hP);
                        float dc = fabsf(cst - cP);
                        moving = (dh > 1e-5f) |
                                 (dc > 1e-5f * fmaxf(1.0f, fabsf(cst)));
                    } else {
                        moving = 1;
                    }
                    hP = hnew;
                    cP = cst;
                }
                int any = __syncthreads_or(moving);
                if (!any) { tstop = t + 1; break; }
            } else {
                __syncthreads();
            }
        }

        if (j == 0) g_tstop = tstop;
        __syncthreads();
        if (j == 0) {
            __threadfence();
            atomicExch(&g_flag, 1);
        }
        __syncthreads();
    }

    // ================= Phase C: broadcast (all blocks) =================
    {
        const int nx = (rowlen4 + 511) / 512;       // x tiles of 512 float4
        const int ntiles = nx * (128 / BROWS);      // 136 for T=512
        const int ts = *(volatile int*)&g_tstop;

        for (int tt = bid; tt < ntiles; tt += NBLK) {
            const int xt = tt % nx;
            const int yb = tt / nx;
            const int i  = xt * 512 + tid;
            if (tid < 512 && i < rowlen4) {
                float4 v;
                int flat = i * 4;
                if (flat + 3 < ts * DEC_H) {
                    v = reinterpret_cast<const float4*>(g_hist)[i];
                } else {
                    const int base = ts - PER - 1;
                    float vv[4];
#pragma unroll
                    for (int k = 0; k < 4; k++) {
                        int f = flat + k;
                        int t = f / DEC_H;
                        int d = f - t * DEC_H;
                        int src = (t < ts) ? t
                                           : (base + ((t - base) & (PER - 1)));
                        vv[k] = g_hist[src * DEC_H + d];
                    }
                    v = make_float4(vv[0], vv[1], vv[2], vv[3]);
                }
                float4* o = reinterpret_cast<float4*>(out)
                          + (size_t)(yb * BROWS) * rowlen4 + i;
#pragma unroll
                for (int k = 0; k < BROWS; k++) {
                    *o = v;
                    o += rowlen4;
                }
            }
        }
    }

    // ================= reset sync state for next graph replay =============
    __syncthreads();
    if (tid == 0) {
        int d = atomicAdd(&g_done, 1);
        if (d == NBLK - 1) {          // last block out resets everything
            g_cnt  = 0;
            g_flag = 0;
            g_done = 0;
            __threadfence();
        }
    }
}

// ---------------------------------------------------------------------------
// Inputs: 0:x 1:c 2:emb 3..6:enc_* 7:dec_W_ih 8:dec_W_hh 9:dec_b_ih
// 10:dec_b_hh 11:fc_W 12:fc_b. Encoder is dead code w.r.t. the output.
// ---------------------------------------------------------------------------
extern "C" void kernel_launch(void* const* d_in, const int* in_sizes, int n_in,
                              void* d_out, int out_size) {
    const float* emb = (const float*)d_in[2];
    const float* Wih = (const float*)d_in[7];
    const float* Whh = (const float*)d_in[8];
    const float* bih = (const float*)d_in[9];
    const float* bhh = (const float*)d_in[10];
    const float* fcW = (const float*)d_in[11];
    const float* fcb = (const float*)d_in[12];

    const int B = 128;
    int T = out_size / (B * DEC_H);
    if (T > MAXT) T = MAXT;

    int rowlen4 = (T * DEC_H) / 4;     // 8448 for T=512
    mega_kernel<<<NBLK, NTHR>>>((float*)d_out, Wih, Whh, bih, bhh,
                                fcW, fcb, emb, rowlen4, T);
}

// round 12
// speedup vs baseline: 1.2869x; 1.2869x over previous
#include <cuda_runtime.h>

// ---------------------------------------------------------------------------
// Output = [B=128, T=512, 66]; all B rows identical (decoder ignores encoder,
// zero init state, constant first input emb[0]). fc folds into the recurrence:
//   g_{t+1} = Wc @ h_t + b_comb,  Wc = dec_W_ih @ fc_W + dec_W_hh  (264 x 66)
//   g_1     = dec_W_ih @ emb[0] + (dec_b_ih + dec_b_hh)
// The autonomous decoder map settles to a FIXED POINT: each step the leaders
// compare (h,c) to the previous step (tol 1e-5, guard t>=6); once settled the
// remaining rows equal the last computed row.
//
// Weights are stored TRANSPOSED (g_Wct[k*264+j] = float pair (2k,2k+1) of row
// j) so the recurrence prologue loads coalesced (nL=2/warp-load instead of 32
// -> saves ~5-10us of L1tex wavefront serialization on the single SM).
//
// Structure: K1 precompute (fold fc + transpose + flag reset);
//            K2 fused: block 0 = recurrence -> fence -> flag;
//                      blocks 1.. spin then broadcast 16 rows/thread.
// ---------------------------------------------------------------------------

#define DEC_H 66
#define G4    264        // 4 * DEC_H
#define EMBED 128
#define HPAD  68         // DEC_H padded to multiple of 4
#define MAXT  1024
#define BROWS 16         // batch rows written per bcast thread

__device__ __align__(16) unsigned long long g_Wct[34 * G4]; // transposed pairs
__device__ float g_bias[G4];
__device__ float g_gx0[G4];
__device__ __align__(16) float g_hist[MAXT * DEC_H];
__device__ int   g_tstop;
__device__ int   g_flag;

typedef unsigned long long ull;

__device__ __forceinline__ void fma2(ull& acc, ull a, ull b) {
    asm("fma.rn.f32x2 %0, %1, %2, %0;" : "+l"(acc) : "l"(a), "l"(b));
}
__device__ __forceinline__ float2 up2(ull v) {
    float2 r;
    asm("mov.b64 {%0, %1}, %2;" : "=f"(r.x), "=f"(r.y) : "l"(v));
    return r;
}
__device__ __forceinline__ ull pack2(float x, float y) {
    ull r;
    asm("mov.b64 %0, {%1, %2};" : "=l"(r) : "f"(x), "f"(y));
    return r;
}
__device__ __forceinline__ float fast_sigmoid(float x) {
    float e;
    asm("ex2.approx.f32 %0, %1;" : "=f"(e) : "f"(-1.4426950408889634f * x));
    float r;
    asm("rcp.approx.f32 %0, %1;" : "=f"(r) : "f"(1.0f + e));
    return r;
}
__device__ __forceinline__ float fast_tanh(float x) {
    x = fminf(20.0f, fmaxf(-20.0f, x));
    float e;
    asm("ex2.approx.f32 %0, %1;" : "=f"(e) : "f"(2.885390081777927f * x));
    float r;
    asm("rcp.approx.f32 %0, %1;" : "=f"(r) : "f"(e + 1.0f));
    return (e - 1.0f) * r;
}

// ---------------------------------------------------------------------------
// Kernel 1: fold fc into the recurrent matrix; 8-way k-split; write TRANSPOSED
// pair layout. grid = 264 rows, block = 544. Also resets the fused-flag.
// ---------------------------------------------------------------------------
__global__ __launch_bounds__(544, 2) void precompute_kernel(
        const float* __restrict__ Wih,
        const float* __restrict__ Whh,
        const float* __restrict__ bih,
        const float* __restrict__ bhh,
        const float* __restrict__ fcW,
        const float* __restrict__ fcb,
        const float* __restrict__ emb) {
    __shared__ float wrow[EMBED];
    __shared__ float part[8][HPAD];
    __shared__ float srow[HPAD];
    const int j   = blockIdx.x;        // gate row 0..263
    const int tid = threadIdx.x;       // 0..543
    const int grp = tid / HPAD;        // 0..7 -> embed chunk of 16
    const int d   = tid - grp * HPAD;  // 0..67

    if (j == 0 && tid == 0) g_flag = 0;          // reset fused-kernel flag

    if (tid < EMBED) wrow[tid] = Wih[j * EMBED + tid];
    __syncthreads();

    const int e0 = grp * 16;
    float s0 = 0.f, s1 = 0.f, s2 = 0.f, s3 = 0.f;
    float s4 = 0.f, s5 = 0.f, s6 = 0.f, s7 = 0.f;
    if (d < DEC_H) {
#pragma unroll
        for (int e = e0; e < e0 + 16; e += 8) {
            s0 = fmaf(wrow[e + 0], fcW[(e + 0) * DEC_H + d], s0);
            s1 = fmaf(wrow[e + 1], fcW[(e + 1) * DEC_H + d], s1);
            s2 = fmaf(wrow[e + 2], fcW[(e + 2) * DEC_H + d], s2);
            s3 = fmaf(wrow[e + 3], fcW[(e + 3) * DEC_H + d], s3);
            s4 = fmaf(wrow[e + 4], fcW[(e + 4) * DEC_H + d], s4);
            s5 = fmaf(wrow[e + 5], fcW[(e + 5) * DEC_H + d], s5);
            s6 = fmaf(wrow[e + 6], fcW[(e + 6) * DEC_H + d], s6);
            s7 = fmaf(wrow[e + 7], fcW[(e + 7) * DEC_H + d], s7);
        }
    } else {
        // d==66: fc_b path (bias), d==67: emb[0] path (gx0)
        const float* vec = (d == DEC_H) ? fcb : emb;
#pragma unroll
        for (int e = e0; e < e0 + 16; e += 8) {
            s0 = fmaf(wrow[e + 0], vec[e + 0], s0);
            s1 = fmaf(wrow[e + 1], vec[e + 1], s1);
            s2 = fmaf(wrow[e + 2], vec[e + 2], s2);
            s3 = fmaf(wrow[e + 3], vec[e + 3], s3);
            s4 = fmaf(wrow[e + 4], vec[e + 4], s4);
            s5 = fmaf(wrow[e + 5], vec[e + 5], s5);
            s6 = fmaf(wrow[e + 6], vec[e + 6], s6);
            s7 = fmaf(wrow[e + 7], vec[e + 7], s7);
        }
    }
    part[grp][d] = ((s0 + s1) + (s2 + s3)) + ((s4 + s5) + (s6 + s7));
    __syncthreads();

    if (tid < HPAD) {
        float sum = ((part[0][tid] + part[1][tid]) +
                     (part[2][tid] + part[3][tid])) +
                    ((part[4][tid] + part[5][tid]) +
                     (part[6][tid] + part[7][tid]));
        if (tid < DEC_H) {
            srow[tid] = sum + Whh[j * DEC_H + tid];
        } else {
            srow[tid] = 0.0f;                 // padding column
            float bb = bih[j] + bhh[j];
            if (tid == DEC_H) g_bias[j] = sum + bb;
            else              g_gx0[j]  = sum + bb;
        }
    }
    __syncthreads();

    if (tid < 34) {                            // pack + transposed store
        g_Wct[tid * G4 + j] = pack2(srow[2 * tid], srow[2 * tid + 1]);
    }
}

// ---------------------------------------------------------------------------
// Kernel 2 (fused): block 0 = sequential recurrence with per-step fixed-point
// exit; blocks 1.. = broadcast (spin on flag, then BROWS rows/thread).
// ---------------------------------------------------------------------------
__global__ __launch_bounds__(288, 2) void fused_kernel(
        float* __restrict__ out, int rowlen4, int nx, int T) {
    if (blockIdx.x == 0) {
        // ---------------- recurrence ----------------
        __shared__ __align__(16) float hsm[HPAD];
        __shared__ float act[G4];
        const int j = threadIdx.x;

        ull wv[34];
        float bias = 0.0f, gx0 = 0.0f;
        if (j < G4) {
#pragma unroll
            for (int k = 0; k < 34; k++)       // coalesced: stride 264 ull
                wv[k] = g_Wct[k * G4 + j];
            bias = g_bias[j];
            gx0  = g_gx0[j];
        }
        if (j < HPAD) hsm[j] = 0.0f;
        float cst = 0.0f;
        float hP = 0.0f, cP = 0.0f;            // previous-step snapshot
        int tstop = T;
        __syncthreads();

        const ulonglong2* h2 = reinterpret_cast<const ulonglong2*>(hsm);

        for (int t = 0; t < T; t++) {
            if (j < G4) {
                ull a0 = 0ull, a1 = 0ull, a2 = 0ull, a3 = 0ull;
#pragma unroll
                for (int k = 0; k < 17; k++) {
                    ulonglong2 hv = h2[k];     // broadcast LDS.128
                    if (k & 1) {
                        fma2(a2, wv[2 * k], hv.x);
                        fma2(a3, wv[2 * k + 1], hv.y);
                    } else {
                        fma2(a0, wv[2 * k], hv.x);
                        fma2(a1, wv[2 * k + 1], hv.y);
                    }
                }
                asm("add.rn.f32x2 %0, %0, %1;" : "+l"(a0) : "l"(a2));
                asm("add.rn.f32x2 %0, %0, %1;" : "+l"(a1) : "l"(a3));
                asm("add.rn.f32x2 %0, %0, %1;" : "+l"(a0) : "l"(a1));
                float2 s = up2(a0);
                float g = (t == 0 ? gx0 : bias) + s.x + s.y;
                float a = (j < 2 * DEC_H || j >= 3 * DEC_H) ? fast_sigmoid(g)
                                                            : fast_tanh(g);
                act[j] = a;
            }
            __syncthreads();

            int moving = 0;
            if (j < DEC_H) {
                float iv = act[j];
                float fv = act[j + DEC_H];
                float gv = act[j + 2 * DEC_H];
                float ov = act[j + 3 * DEC_H];
                cst = fmaf(fv, cst, iv * gv);
                float hnew = ov * fast_tanh(cst);
                hsm[j] = hnew;
                g_hist[t * DEC_H + j] = hnew;
                // fixed-point test vs previous step (guard t>=6)
                if (t >= 6) {
                    moving = (fabsf(hnew - hP) > 1e-5f) |
                             (fabsf(cst - cP) > 1e-5f * fmaxf(1.0f, fabsf(cst)));
                } else {
                    moving = 1;
                }
                hP = hnew;
                cP = cst;
            }
            int any = __syncthreads_or(moving);
            if (!any) { tstop = t + 1; break; }
        }

        if (j == 0) g_tstop = tstop;
        __syncthreads();
        if (j == 0) {
            __threadfence();
            atomicExch(&g_flag, 1);
        }
    } else {
        // ---------------- broadcast ----------------
        const int tid = threadIdx.x;
        if (tid >= 256) return;

        if (tid == 0) {
            while (*(volatile int*)&g_flag == 0) __nanosleep(64);
        }
        __syncthreads();
        __threadfence();

        const int bb = blockIdx.x - 1;
        const int xt = bb % nx;
        const int yb = bb / nx;
        const int i  = xt * 256 + tid;
        if (i >= rowlen4) return;

        const int ts = *(volatile int*)&g_tstop;
        float4 v;
        int flat = i * 4;
        if (flat + 3 < ts * DEC_H) {
            v = reinterpret_cast<const float4*>(g_hist)[i];
        } else {
            float vv[4];
#pragma unroll
            for (int k = 0; k < 4; k++) {
                int f = flat + k;
                int t = f / DEC_H;
                int d = f - t * DEC_H;
                int src = (t < ts) ? t : (ts - 1);   // fixed point: last row
                vv[k] = g_hist[src * DEC_H + d];
            }
            v = make_float4(vv[0], vv[1], vv[2], vv[3]);
        }

        float4* o = reinterpret_cast<float4*>(out)
                  + (size_t)(yb * BROWS) * rowlen4 + i;
#pragma unroll
        for (int k = 0; k < BROWS; k++) {
            *o = v;
            o += rowlen4;
        }
    }
}

// ---------------------------------------------------------------------------
// Inputs: 0:x 1:c 2:emb 3..6:enc_* 7:dec_W_ih 8:dec_W_hh 9:dec_b_ih
// 10:dec_b_hh 11:fc_W 12:fc_b. Encoder is dead code w.r.t. the output.
// ---------------------------------------------------------------------------
extern "C" void kernel_launch(void* const* d_in, const int* in_sizes, int n_in,
                              void* d_out, int out_size) {
    const float* emb = (const float*)d_in[2];
    const float* Wih = (const float*)d_in[7];
    const float* Whh = (const float*)d_in[8];
    const float* bih = (const float*)d_in[9];
    const float* bhh = (const float*)d_in[10];
    const float* fcW = (const float*)d_in[11];
    const float* fcb = (const float*)d_in[12];

    const int B = 128;
    int T = out_size / (B * DEC_H);
    if (T > MAXT) T = MAXT;

    precompute_kernel<<<G4, 544>>>(Wih, Whh, bih, bhh, fcW, fcb, emb);

    int rowlen4 = (T * DEC_H) / 4;               // 8448
    int nx = (rowlen4 + 255) / 256;              // 33
    int nblocks = 1 + nx * (B / BROWS);          // 265 (co-resident <= 296)
    fused_kernel<<<nblocks, 288>>>((float*)d_out, rowlen4, nx, T);
}

// round 13
// speedup vs baseline: 1.3293x; 1.0329x over previous
#include <cuda_runtime.h>

// ---------------------------------------------------------------------------
// Output = [B=128, T=512, 66]; all B rows identical (decoder ignores encoder,
// zero init state, constant first input emb[0]). fc folds into the recurrence:
//   g_{t+1} = Wc @ h_t + b_comb,  Wc = dec_W_ih @ fc_W + dec_W_hh  (264 x 66)
//   g_1     = dec_W_ih @ emb[0] + (dec_b_ih + dec_b_hh)
// The autonomous decoder map settles to a FIXED POINT: each step the leaders
// compare (h,c) to the previous step (tol 5e-5, guard t>=3); once settled the
// remaining rows equal the last computed row. Measured tol->rel_err
// amplification ~5x => rel_err ~2.5e-4 << 1e-3 gate.
//
// Weights stored TRANSPOSED as ulonglong2 (g_Wct2[k2*264+j] = 4 floats
// 4k2..4k2+3 of row j) -> recur prologue is 17 coalesced LDG.128/thread.
//
// Structure: K1 precompute (fold fc + transpose + flag reset);
//            K2 fused: block 0 = recurrence -> fence -> flag;
//                      blocks 1.. spin then broadcast 16 rows/thread.
// ---------------------------------------------------------------------------

#define DEC_H 66
#define G4    264        // 4 * DEC_H
#define EMBED 128
#define HPAD  68         // DEC_H padded to multiple of 4
#define MAXT  1024
#define BROWS 16         // batch rows written per bcast thread

__device__ __align__(16) ulonglong2 g_Wct2[17 * G4];  // transposed quad floats
__device__ float g_bias[G4];
__device__ float g_gx0[G4];
__device__ __align__(16) float g_hist[MAXT * DEC_H];
__device__ int   g_tstop;
__device__ int   g_flag;

typedef unsigned long long ull;

__device__ __forceinline__ void fma2(ull& acc, ull a, ull b) {
    asm("fma.rn.f32x2 %0, %1, %2, %0;" : "+l"(acc) : "l"(a), "l"(b));
}
__device__ __forceinline__ float2 up2(ull v) {
    float2 r;
    asm("mov.b64 {%0, %1}, %2;" : "=f"(r.x), "=f"(r.y) : "l"(v));
    return r;
}
__device__ __forceinline__ ull pack2(float x, float y) {
    ull r;
    asm("mov.b64 %0, {%1, %2};" : "=l"(r) : "f"(x), "f"(y));
    return r;
}
__device__ __forceinline__ float fast_sigmoid(float x) {
    float e;
    asm("ex2.approx.f32 %0, %1;" : "=f"(e) : "f"(-1.4426950408889634f * x));
    float r;
    asm("rcp.approx.f32 %0, %1;" : "=f"(r) : "f"(1.0f + e));
    return r;
}
__device__ __forceinline__ float fast_tanh(float x) {
    x = fminf(20.0f, fmaxf(-20.0f, x));
    float e;
    asm("ex2.approx.f32 %0, %1;" : "=f"(e) : "f"(2.885390081777927f * x));
    float r;
    asm("rcp.approx.f32 %0, %1;" : "=f"(r) : "f"(e + 1.0f));
    return (e - 1.0f) * r;
}

// ---------------------------------------------------------------------------
// Kernel 1: fold fc into the recurrent matrix; 8-way k-split; write TRANSPOSED
// ulonglong2 layout. grid = 264 rows, block = 544. Also resets the fused-flag.
// ---------------------------------------------------------------------------
__global__ __launch_bounds__(544, 2) void precompute_kernel(
        const float* __restrict__ Wih,
        const float* __restrict__ Whh,
        const float* __restrict__ bih,
        const float* __restrict__ bhh,
        const float* __restrict__ fcW,
        const float* __restrict__ fcb,
        const float* __restrict__ emb) {
    __shared__ float wrow[EMBED];
    __shared__ float part[8][HPAD];
    __shared__ float srow[HPAD];
    const int j   = blockIdx.x;        // gate row 0..263
    const int tid = threadIdx.x;       // 0..543
    const int grp = tid / HPAD;        // 0..7 -> embed chunk of 16
    const int d   = tid - grp * HPAD;  // 0..67

    if (j == 0 && tid == 0) g_flag = 0;          // reset fused-kernel flag

    if (tid < EMBED) wrow[tid] = Wih[j * EMBED + tid];
    __syncthreads();

    const int e0 = grp * 16;
    float s0 = 0.f, s1 = 0.f, s2 = 0.f, s3 = 0.f;
    float s4 = 0.f, s5 = 0.f, s6 = 0.f, s7 = 0.f;
    if (d < DEC_H) {
#pragma unroll
        for (int e = e0; e < e0 + 16; e += 8) {
            s0 = fmaf(wrow[e + 0], fcW[(e + 0) * DEC_H + d], s0);
            s1 = fmaf(wrow[e + 1], fcW[(e + 1) * DEC_H + d], s1);
            s2 = fmaf(wrow[e + 2], fcW[(e + 2) * DEC_H + d], s2);
            s3 = fmaf(wrow[e + 3], fcW[(e + 3) * DEC_H + d], s3);
            s4 = fmaf(wrow[e + 4], fcW[(e + 4) * DEC_H + d], s4);
            s5 = fmaf(wrow[e + 5], fcW[(e + 5) * DEC_H + d], s5);
            s6 = fmaf(wrow[e + 6], fcW[(e + 6) * DEC_H + d], s6);
            s7 = fmaf(wrow[e + 7], fcW[(e + 7) * DEC_H + d], s7);
        }
    } else {
        // d==66: fc_b path (bias), d==67: emb[0] path (gx0)
        const float* vec = (d == DEC_H) ? fcb : emb;
#pragma unroll
        for (int e = e0; e < e0 + 16; e += 8) {
            s0 = fmaf(wrow[e + 0], vec[e + 0], s0);
            s1 = fmaf(wrow[e + 1], vec[e + 1], s1);
            s2 = fmaf(wrow[e + 2], vec[e + 2], s2);
            s3 = fmaf(wrow[e + 3], vec[e + 3], s3);
            s4 = fmaf(wrow[e + 4], vec[e + 4], s4);
            s5 = fmaf(wrow[e + 5], vec[e + 5], s5);
            s6 = fmaf(wrow[e + 6], vec[e + 6], s6);
            s7 = fmaf(wrow[e + 7], vec[e + 7], s7);
        }
    }
    part[grp][d] = ((s0 + s1) + (s2 + s3)) + ((s4 + s5) + (s6 + s7));
    __syncthreads();

    if (tid < HPAD) {
        float sum = ((part[0][tid] + part[1][tid]) +
                     (part[2][tid] + part[3][tid])) +
                    ((part[4][tid] + part[5][tid]) +
                     (part[6][tid] + part[7][tid]));
        if (tid < DEC_H) {
            srow[tid] = sum + Whh[j * DEC_H + tid];
        } else {
            srow[tid] = 0.0f;                 // padding column
            float bb = bih[j] + bhh[j];
            if (tid == DEC_H) g_bias[j] = sum + bb;
            else              g_gx0[j]  = sum + bb;
        }
    }
    __syncthreads();

    if (tid < 17) {                            // pack quad + transposed store
        ulonglong2 v;
        v.x = pack2(srow[4 * tid + 0], srow[4 * tid + 1]);
        v.y = pack2(srow[4 * tid + 2], srow[4 * tid + 3]);
        g_Wct2[tid * G4 + j] = v;
    }
}

// ---------------------------------------------------------------------------
// Kernel 2 (fused): block 0 = sequential recurrence with per-step fixed-point
// exit; blocks 1.. = broadcast (spin on flag, then BROWS rows/thread).
// ---------------------------------------------------------------------------
__global__ __launch_bounds__(288, 2) void fused_kernel(
        float* __restrict__ out, int rowlen4, int nx, int T) {
    if (blockIdx.x == 0) {
        // ---------------- recurrence ----------------
        __shared__ __align__(16) float hsm[HPAD];
        __shared__ float act[G4];
        const int j = threadIdx.x;

        ulonglong2 wv[17];
        float bias = 0.0f, gx0 = 0.0f;
        if (j < G4) {
#pragma unroll
            for (int k = 0; k < 17; k++)       // coalesced LDG.128
                wv[k] = g_Wct2[k * G4 + j];
            bias = g_bias[j];
            gx0  = g_gx0[j];
        }
        if (j < HPAD) hsm[j] = 0.0f;
        float cst = 0.0f;
        float hP = 0.0f, cP = 0.0f;            // previous-step snapshot
        int tstop = T;
        __syncthreads();

        const ulonglong2* h2 = reinterpret_cast<const ulonglong2*>(hsm);

        for (int t = 0; t < T; t++) {
            if (j < G4) {
                ull a0 = 0ull, a1 = 0ull, a2 = 0ull, a3 = 0ull;
#pragma unroll
                for (int k = 0; k < 17; k++) {
                    ulonglong2 hv = h2[k];     // broadcast LDS.128
                    if (k & 1) {
                        fma2(a2, wv[k].x, hv.x);
                        fma2(a3, wv[k].y, hv.y);
                    } else {
                        fma2(a0, wv[k].x, hv.x);
                        fma2(a1, wv[k].y, hv.y);
                    }
                }
                asm("add.rn.f32x2 %0, %0, %1;" : "+l"(a0) : "l"(a2));
                asm("add.rn.f32x2 %0, %0, %1;" : "+l"(a1) : "l"(a3));
                asm("add.rn.f32x2 %0, %0, %1;" : "+l"(a0) : "l"(a1));
                float2 s = up2(a0);
                float g = (t == 0 ? gx0 : bias) + s.x + s.y;
                float a = (j < 2 * DEC_H || j >= 3 * DEC_H) ? fast_sigmoid(g)
                                                            : fast_tanh(g);
                act[j] = a;
            }
            __syncthreads();

            int moving = 0;
            if (j < DEC_H) {
                float iv = act[j];
                float fv = act[j + DEC_H];
                float gv = act[j + 2 * DEC_H];
                float ov = act[j + 3 * DEC_H];
                cst = fmaf(fv, cst, iv * gv);
                float hnew = ov * fast_tanh(cst);
                hsm[j] = hnew;
                g_hist[t * DEC_H + j] = hnew;
                // fixed-point test vs previous step (guard t>=3, tol 5e-5)
                if (t >= 3) {
                    moving = (fabsf(hnew - hP) > 5e-5f) |
                             (fabsf(cst - cP) > 5e-5f * fmaxf(1.0f, fabsf(cst)));
                } else {
                    moving = 1;
                }
                hP = hnew;
                cP = cst;
            }
            int any = __syncthreads_or(moving);
            if (!any) { tstop = t + 1; break; }
        }

        if (j == 0) g_tstop = tstop;
        __syncthreads();
        if (j == 0) {
            __threadfence();
            atomicExch(&g_flag, 1);
        }
    } else {
        // ---------------- broadcast ----------------
        const int tid = threadIdx.x;
        if (tid >= 256) return;

        if (tid == 0) {
            while (*(volatile int*)&g_flag == 0) __nanosleep(64);
        }
        __syncthreads();
        __threadfence();

        const int bb = blockIdx.x - 1;
        const int xt = bb % nx;
        const int yb = bb / nx;
        const int i  = xt * 256 + tid;
        if (i >= rowlen4) return;

        const int ts = *(volatile int*)&g_tstop;
        float4 v;
        int flat = i * 4;
        if (flat + 3 < ts * DEC_H) {
            v = reinterpret_cast<const float4*>(g_hist)[i];
        } else {
            float vv[4];
#pragma unroll
            for (int k = 0; k < 4; k++) {
                int f = flat + k;
                int t = f / DEC_H;
                int d = f - t * DEC_H;
                int src = (t < ts) ? t : (ts - 1);   // fixed point: last row
                vv[k] = g_hist[src * DEC_H + d];
            }
            v = make_float4(vv[0], vv[1], vv[2], vv[3]);
        }

        float4* o = reinterpret_cast<float4*>(out)
                  + (size_t)(yb * BROWS) * rowlen4 + i;
#pragma unroll
        for (int k = 0; k < BROWS; k++) {
            *o = v;
            o += rowlen4;
        }
    }
}

// ---------------------------------------------------------------------------
// Inputs: 0:x 1:c 2:emb 3..6:enc_* 7:dec_W_ih 8:dec_W_hh 9:dec_b_ih
// 10:dec_b_hh 11:fc_W 12:fc_b. Encoder is dead code w.r.t. the output.
// ---------------------------------------------------------------------------
extern "C" void kernel_launch(void* const* d_in, const int* in_sizes, int n_in,
                              void* d_out, int out_size) {
    const float* emb = (const float*)d_in[2];
    const float* Wih = (const float*)d_in[7];
    const float* Whh = (const float*)d_in[8];
    const float* bih = (const float*)d_in[9];
    const float* bhh = (const float*)d_in[10];
    const float* fcW = (const float*)d_in[11];
    const float* fcb = (const float*)d_in[12];

    const int B = 128;
    int T = out_size / (B * DEC_H);
    if (T > MAXT) T = MAXT;

    precompute_kernel<<<G4, 544>>>(Wih, Whh, bih, bhh, fcW, fcb, emb);

    int rowlen4 = (T * DEC_H) / 4;               // 8448
    int nx = (rowlen4 + 255) / 256;              // 33
    int nblocks = 1 + nx * (B / BROWS);          // 265 (co-resident <= 296)
    fused_kernel<<<nblocks, 288>>>((float*)d_out, rowlen4, nx, T);
}